// round 2
// baseline (speedup 1.0000x reference)
#include <cuda_runtime.h>
#include <math.h>

#define D_MODEL 512
#define STATE_N 64
#define BATCH   4
#define SEQ     2048
#define M_ROWS  (BATCH*SEQ)      // 8192
#define NC      16               // time chunks
#define LCH     (SEQ/NC)         // 128 steps per chunk
#define BD      (BATCH*D_MODEL)  // 2048

// ------------------------- scratch (device globals; no allocs allowed) ----
__device__ __align__(256) float  g_u   [M_ROWS*D_MODEL];
__device__ __align__(256) float  g_gate[M_ROWS*D_MODEL];
__device__ __align__(256) float  g_y   [M_ROWS*D_MODEL];
__device__ __align__(256) float2 g_S   [NC*BD*STATE_N];
__device__ __align__(256) float2 g_E   [NC*BD*STATE_N];
__device__ __align__(256) float  g_wr  [D_MODEL*STATE_N];
__device__ __align__(256) float  g_wi  [D_MODEL*STATE_N];
__device__ __align__(256) float  g_cb  [D_MODEL*STATE_N];
__device__ __align__(256) float  g_wLr [D_MODEL*STATE_N];
__device__ __align__(256) float  g_wLi [D_MODEL*STATE_N];

// ------------------------- f32x2 helpers ---------------------------------
__device__ __forceinline__ unsigned long long ffma2(unsigned long long a,
                                                    unsigned long long b,
                                                    unsigned long long c) {
    unsigned long long d;
    asm("fma.rn.f32x2 %0, %1, %2, %3;" : "=l"(d) : "l"(a), "l"(b), "l"(c));
    return d;
}
__device__ __forceinline__ unsigned long long pk2(float x, float y) {
    unsigned long long r;
    asm("mov.b64 %0, {%1, %2};" : "=l"(r) : "r"(__float_as_uint(x)), "r"(__float_as_uint(y)));
    return r;
}
__device__ __forceinline__ float2 up2(unsigned long long v) {
    unsigned int lo, hi;
    asm("mov.b64 {%0, %1}, %2;" : "=r"(lo), "=r"(hi) : "l"(v));
    return make_float2(__uint_as_float(lo), __uint_as_float(hi));
}

// ------------------------- SSM parameter precompute -----------------------
// w = exp(dt*(-exp(log_A_real) + i*A_imag)) ; cb = C*B*dt ; wL = w^LCH
__global__ void prep_kernel(const float* __restrict__ logAr,
                            const float* __restrict__ Aim,
                            const float* __restrict__ Bp,
                            const float* __restrict__ Cp,
                            const float* __restrict__ logdt) {
    int i = blockIdx.x * blockDim.x + threadIdx.x;
    if (i >= D_MODEL * STATE_N) return;
    int d = i >> 6;
    float dt   = expf(logdt[d]);
    float ar   = -expf(logAr[i]);
    float th   = dt * Aim[i];
    float mag  = expf(dt * ar);
    float wrv  = mag * cosf(th);
    float wiv  = mag * sinf(th);
    g_wr[i] = wrv;
    g_wi[i] = wiv;
    g_cb[i] = Cp[i] * Bp[i] * dt;
    float xr = wrv, xi = wiv;
#pragma unroll
    for (int s = 0; s < 7; s++) {  // 2^7 = 128 = LCH
        float nr = xr * xr - xi * xi;
        float ni = 2.0f * xr * xi;
        xr = nr; xi = ni;
    }
    g_wLr[i] = xr;
    g_wLi[i] = xi;
}

// ------------------------- GEMM: C = A[8192x512] * W[512x512]^T -----------
// MODE 0: g_u   = x @ W_in^T
// MODE 1: g_gate= sigmoid(x @ W_gate^T + b_gate)
// MODE 2: d_out = x + g_gate * (g_y @ W_out^T)
template<int MODE>
__global__ __launch_bounds__(256) void gemm_kernel(
    const float* __restrict__ A_ext,   // x (mode 0,1,2: x for aux in mode2)
    const float* __restrict__ Wm,      // weight [512,512]
    float* __restrict__ C_ext,         // d_out for mode 2, else unused
    const float* __restrict__ bgate) { // b_gate for mode 1, else unused
    __shared__ float As[16][128];
    __shared__ float Bs[16][128];
    const int tid = threadIdx.x;
    const int m0 = blockIdx.x * 128;
    const int n0 = blockIdx.y * 128;
    const int tx = tid & 15;   // n direction
    const int ty = tid >> 4;   // m direction

    const float* A = (MODE == 2) ? g_y : A_ext;
    float* Cout = (MODE == 0) ? g_u : (MODE == 1) ? g_gate : C_ext;

    unsigned long long acc[8][4];
#pragma unroll
    for (int i = 0; i < 8; i++)
#pragma unroll
        for (int j = 0; j < 4; j++) acc[i][j] = 0ull;

    const int lrow = tid >> 1;        // 0..127
    const int lc   = (tid & 1) * 8;   // 0 or 8
    const float* Ap = A  + (size_t)(m0 + lrow) * 512 + lc;
    const float* Bp = Wm + (size_t)(n0 + lrow) * 512 + lc;

    for (int kt = 0; kt < 512; kt += 16) {
        float4 a0 = *(const float4*)(Ap + kt);
        float4 a1 = *(const float4*)(Ap + kt + 4);
        float4 b0 = *(const float4*)(Bp + kt);
        float4 b1 = *(const float4*)(Bp + kt + 4);
        __syncthreads();
        As[lc+0][lrow]=a0.x; As[lc+1][lrow]=a0.y; As[lc+2][lrow]=a0.z; As[lc+3][lrow]=a0.w;
        As[lc+4][lrow]=a1.x; As[lc+5][lrow]=a1.y; As[lc+6][lrow]=a1.z; As[lc+7][lrow]=a1.w;
        Bs[lc+0][lrow]=b0.x; Bs[lc+1][lrow]=b0.y; Bs[lc+2][lrow]=b0.z; Bs[lc+3][lrow]=b0.w;
        Bs[lc+4][lrow]=b1.x; Bs[lc+5][lrow]=b1.y; Bs[lc+6][lrow]=b1.z; Bs[lc+7][lrow]=b1.w;
        __syncthreads();
#pragma unroll
        for (int kk = 0; kk < 16; kk++) {
            const ulonglong2* bpv = (const ulonglong2*)&Bs[kk][tx * 8];
            ulonglong2 bq0 = bpv[0];
            ulonglong2 bq1 = bpv[1];
            float4 av0 = *(const float4*)&As[kk][ty * 8];
            float4 av1 = *(const float4*)&As[kk][ty * 8 + 4];
            unsigned long long bp4[4] = {bq0.x, bq0.y, bq1.x, bq1.y};
            float am[8] = {av0.x, av0.y, av0.z, av0.w, av1.x, av1.y, av1.z, av1.w};
#pragma unroll
            for (int mi = 0; mi < 8; mi++) {
                unsigned long long ad = pk2(am[mi], am[mi]);
#pragma unroll
                for (int np = 0; np < 4; np++)
                    acc[mi][np] = ffma2(ad, bp4[np], acc[mi][np]);
            }
        }
    }

    // epilogue
    const int ncol = n0 + tx * 8;
    float bias[8];
    if (MODE == 1) {
        float4 bg0 = *(const float4*)(bgate + ncol);
        float4 bg1 = *(const float4*)(bgate + ncol + 4);
        bias[0]=bg0.x; bias[1]=bg0.y; bias[2]=bg0.z; bias[3]=bg0.w;
        bias[4]=bg1.x; bias[5]=bg1.y; bias[6]=bg1.z; bias[7]=bg1.w;
    }
#pragma unroll
    for (int mi = 0; mi < 8; mi++) {
        const int m = m0 + ty * 8 + mi;
        float v[8];
#pragma unroll
        for (int np = 0; np < 4; np++) {
            float2 p = up2(acc[mi][np]);
            v[2*np] = p.x; v[2*np+1] = p.y;
        }
        float* crow = Cout + (size_t)m * 512 + ncol;
        if (MODE == 1) {
#pragma unroll
            for (int j = 0; j < 8; j++)
                v[j] = __fdividef(1.0f, 1.0f + __expf(-(v[j] + bias[j])));
        } else if (MODE == 2) {
            const float* xr = A_ext + (size_t)m * 512 + ncol;
            const float* gr = g_gate + (size_t)m * 512 + ncol;
            float4 x0 = *(const float4*)(xr);
            float4 x1 = *(const float4*)(xr + 4);
            float4 gg0 = *(const float4*)(gr);
            float4 gg1 = *(const float4*)(gr + 4);
            v[0] = fmaf(gg0.x, v[0], x0.x); v[1] = fmaf(gg0.y, v[1], x0.y);
            v[2] = fmaf(gg0.z, v[2], x0.z); v[3] = fmaf(gg0.w, v[3], x0.w);
            v[4] = fmaf(gg1.x, v[4], x1.x); v[5] = fmaf(gg1.y, v[5], x1.y);
            v[6] = fmaf(gg1.z, v[6], x1.z); v[7] = fmaf(gg1.w, v[7], x1.w);
        }
        *(float4*)(crow)     = make_float4(v[0], v[1], v[2], v[3]);
        *(float4*)(crow + 4) = make_float4(v[4], v[5], v[6], v[7]);
    }
}

// ------------------------- scan phase 1: per-chunk local end states -------
// grid (D/32, NC, B); block 256 = 32 channel-groups x 8 lanes (8 states each)
__global__ __launch_bounds__(256) void scan_phase1() {
    __shared__ float Us[LCH][32];
    const int tid  = threadIdx.x;
    const int dblk = blockIdx.x, c = blockIdx.y, b = blockIdx.z;
    const int dd = tid >> 3, j = tid & 7;
    const int d  = dblk * 32 + dd;

    const float* u = g_u + (size_t)(b * SEQ + c * LCH) * 512 + dblk * 32;
    for (int r = tid >> 5; r < LCH; r += 8)
        Us[r][tid & 31] = u[(size_t)r * 512 + (tid & 31)];
    __syncthreads();

    const int nbase = j * 8;
    float wr[8], wi[8], sr[8], si[8];
    {
        const float4* p = (const float4*)(g_wr + d * STATE_N + nbase);
        float4 t0 = p[0], t1 = p[1];
        wr[0]=t0.x; wr[1]=t0.y; wr[2]=t0.z; wr[3]=t0.w;
        wr[4]=t1.x; wr[5]=t1.y; wr[6]=t1.z; wr[7]=t1.w;
        p = (const float4*)(g_wi + d * STATE_N + nbase);
        t0 = p[0]; t1 = p[1];
        wi[0]=t0.x; wi[1]=t0.y; wi[2]=t0.z; wi[3]=t0.w;
        wi[4]=t1.x; wi[5]=t1.y; wi[6]=t1.z; wi[7]=t1.w;
    }
#pragma unroll
    for (int k = 0; k < 8; k++) { sr[k] = 0.0f; si[k] = 0.0f; }

#pragma unroll 4
    for (int t = 0; t < LCH; t++) {
        float ut = Us[t][dd];
#pragma unroll
        for (int k = 0; k < 8; k++) {
            float mm = wi[k] * sr[k];
            sr[k] = fmaf(wr[k], sr[k], fmaf(-wi[k], si[k], ut));
            si[k] = fmaf(wr[k], si[k], mm);
        }
    }
    float2* Sp = g_S + ((size_t)(c * BD + b * D_MODEL + d)) * STATE_N + nbase;
#pragma unroll
    for (int k = 0; k < 8; k++) Sp[k] = make_float2(sr[k], si[k]);
}

// ------------------------- scan phase 2: chunk-carry prefix scan ----------
__global__ __launch_bounds__(256) void scan_phase2() {
    const int i  = blockIdx.x * blockDim.x + threadIdx.x;  // 0 .. BD*64-1
    const int bd = i >> 6;
    const int n  = i & 63;
    const int d  = bd & (D_MODEL - 1);
    const float wLr = g_wLr[d * STATE_N + n];
    const float wLi = g_wLi[d * STATE_N + n];
    float er = 0.0f, ei = 0.0f;
#pragma unroll
    for (int c = 0; c < NC; c++) {
        const size_t idx = ((size_t)c * BD + bd) * STATE_N + n;
        g_E[idx] = make_float2(er, ei);
        float2 s = g_S[idx];
        float nr = fmaf(wLr, er, fmaf(-wLi, ei, s.x));
        float ni = fmaf(wLr, ei, fmaf(wLi, er, s.y));
        er = nr; ei = ni;
    }
}

// ------------------------- scan phase 3: full scan + output ---------------
__global__ __launch_bounds__(256) void scan_phase3(const float* __restrict__ Dp) {
    __shared__ float Us[LCH][32];
    const int tid  = threadIdx.x;
    const int dblk = blockIdx.x, c = blockIdx.y, b = blockIdx.z;
    const int dd = tid >> 3, j = tid & 7;
    const int d  = dblk * 32 + dd;

    const float* u = g_u + (size_t)(b * SEQ + c * LCH) * 512 + dblk * 32;
    for (int r = tid >> 5; r < LCH; r += 8)
        Us[r][tid & 31] = u[(size_t)r * 512 + (tid & 31)];
    __syncthreads();

    const int nbase = j * 8;
    float wr[8], wi[8], cb[8], sr[8], si[8];
    {
        const float4* p = (const float4*)(g_wr + d * STATE_N + nbase);
        float4 t0 = p[0], t1 = p[1];
        wr[0]=t0.x; wr[1]=t0.y; wr[2]=t0.z; wr[3]=t0.w;
        wr[4]=t1.x; wr[5]=t1.y; wr[6]=t1.z; wr[7]=t1.w;
        p = (const float4*)(g_wi + d * STATE_N + nbase);
        t0 = p[0]; t1 = p[1];
        wi[0]=t0.x; wi[1]=t0.y; wi[2]=t0.z; wi[3]=t0.w;
        wi[4]=t1.x; wi[5]=t1.y; wi[6]=t1.z; wi[7]=t1.w;
        p = (const float4*)(g_cb + d * STATE_N + nbase);
        t0 = p[0]; t1 = p[1];
        cb[0]=t0.x; cb[1]=t0.y; cb[2]=t0.z; cb[3]=t0.w;
        cb[4]=t1.x; cb[5]=t1.y; cb[6]=t1.z; cb[7]=t1.w;
    }
    const float2* Ep = g_E + ((size_t)(c * BD + b * D_MODEL + d)) * STATE_N + nbase;
#pragma unroll
    for (int k = 0; k < 8; k++) {
        float2 e = Ep[k];
        sr[k] = e.x; si[k] = e.y;
    }
    const float Dd = Dp[d];
    float* yout = g_y + (size_t)(b * SEQ + c * LCH) * 512 + d;

#pragma unroll 4
    for (int t = 0; t < LCH; t++) {
        float ut = Us[t][dd];
        float accv = 0.0f;
#pragma unroll
        for (int k = 0; k < 8; k++) {
            float mm = wi[k] * sr[k];
            sr[k] = fmaf(wr[k], sr[k], fmaf(-wi[k], si[k], ut));
            si[k] = fmaf(wr[k], si[k], mm);
            accv  = fmaf(cb[k], sr[k], accv);
        }
        accv += __shfl_xor_sync(0xffffffffu, accv, 1, 8);
        accv += __shfl_xor_sync(0xffffffffu, accv, 2, 8);
        accv += __shfl_xor_sync(0xffffffffu, accv, 4, 8);
        if (j == 0) yout[(size_t)t * 512] = fmaf(Dd, ut, accv);
    }
}

// ------------------------- launch ----------------------------------------
extern "C" void kernel_launch(void* const* d_in, const int* in_sizes, int n_in,
                              void* d_out, int out_size) {
    const float* x      = (const float*)d_in[0];
    const float* logAr  = (const float*)d_in[1];
    const float* Aim    = (const float*)d_in[2];
    const float* Bp_    = (const float*)d_in[3];
    const float* Cp_    = (const float*)d_in[4];
    const float* Dp_    = (const float*)d_in[5];
    const float* logdt  = (const float*)d_in[6];
    const float* W_in   = (const float*)d_in[7];
    const float* W_out  = (const float*)d_in[8];
    const float* W_gate = (const float*)d_in[9];
    const float* b_gate = (const float*)d_in[10];
    float* out = (float*)d_out;

    prep_kernel<<<(D_MODEL * STATE_N + 255) / 256, 256>>>(logAr, Aim, Bp_, Cp_, logdt);
    gemm_kernel<0><<<dim3(M_ROWS / 128, 4), 256>>>(x, W_in,   nullptr, nullptr);
    gemm_kernel<1><<<dim3(M_ROWS / 128, 4), 256>>>(x, W_gate, nullptr, b_gate);
    scan_phase1<<<dim3(D_MODEL / 32, NC, BATCH), 256>>>();
    scan_phase2<<<(BD * STATE_N) / 256, 256>>>();
    scan_phase3<<<dim3(D_MODEL / 32, NC, BATCH), 256>>>(Dp_);
    gemm_kernel<2><<<dim3(M_ROWS / 128, 4), 256>>>(x, W_out, out, nullptr);
}

// round 5
// speedup vs baseline: 1.5501x; 1.5501x over previous
#include <cuda_runtime.h>
#include <cuda_bf16.h>
#include <math.h>
#include <stdint.h>

#define D_MODEL 512
#define STATE_N 64
#define BATCH   4
#define SEQ     2048
#define M_ROWS  8192
#define NC      16
#define LCH     128
#define BD      2048
#define KCAT    1536           // 3 * 512 (bf16-split concatenated K)

// ------------------------- scratch (device globals) -----------------------
__device__ __align__(256) float  g_u   [M_ROWS*D_MODEL];
__device__ __align__(256) float  g_gate[M_ROWS*D_MODEL];
__device__ __align__(256) float  g_y   [M_ROWS*D_MODEL];
__device__ __align__(256) float2 g_S   [NC*BD*STATE_N];
__device__ __align__(256) float2 g_E   [NC*BD*STATE_N];
__device__ __align__(256) float  g_wr  [D_MODEL*STATE_N];
__device__ __align__(256) float  g_wi  [D_MODEL*STATE_N];
__device__ __align__(256) float  g_cb  [D_MODEL*STATE_N];
__device__ __align__(256) float  g_wLr [D_MODEL*STATE_N];
__device__ __align__(256) float  g_wLi [D_MODEL*STATE_N];
__device__ __align__(256) __nv_bfloat16 g_xcat  [M_ROWS*KCAT];
__device__ __align__(256) __nv_bfloat16 g_ycat  [M_ROWS*KCAT];
__device__ __align__(256) __nv_bfloat16 g_wincat[D_MODEL*KCAT];
__device__ __align__(256) __nv_bfloat16 g_wgcat [D_MODEL*KCAT];
__device__ __align__(256) __nv_bfloat16 g_wocat [D_MODEL*KCAT];

// ------------------------- f32x2 / ptx helpers ----------------------------
__device__ __forceinline__ unsigned long long ffma2(unsigned long long a,
                                                    unsigned long long b,
                                                    unsigned long long c) {
    unsigned long long d;
    asm("fma.rn.f32x2 %0, %1, %2, %3;" : "=l"(d) : "l"(a), "l"(b), "l"(c));
    return d;
}
__device__ __forceinline__ unsigned long long mul2(unsigned long long a,
                                                   unsigned long long b) {
    unsigned long long d;
    asm("mul.rn.f32x2 %0, %1, %2;" : "=l"(d) : "l"(a), "l"(b));
    return d;
}
__device__ __forceinline__ unsigned long long pk2(float x, float y) {
    unsigned long long r;
    asm("mov.b64 %0, {%1, %2};" : "=l"(r) : "r"(__float_as_uint(x)), "r"(__float_as_uint(y)));
    return r;
}
__device__ __forceinline__ float2 up2(unsigned long long v) {
    unsigned int lo, hi;
    asm("mov.b64 {%0, %1}, %2;" : "=r"(lo), "=r"(hi) : "l"(v));
    return make_float2(__uint_as_float(lo), __uint_as_float(hi));
}
__device__ __forceinline__ uint32_t smem_u32(const void* p) {
    uint32_t a;
    asm("{ .reg .u64 t; cvta.to.shared.u64 t, %1; cvt.u32.u64 %0, t; }" : "=r"(a) : "l"(p));
    return a;
}
__device__ __forceinline__ uint32_t sw128(uint32_t off) {
    return off ^ ((off >> 3) & 0x70);
}
__device__ __forceinline__ void ldmx4(uint32_t* r, uint32_t addr) {
    asm volatile("ldmatrix.sync.aligned.m8n8.x4.shared.b16 {%0,%1,%2,%3}, [%4];"
                 : "=r"(r[0]), "=r"(r[1]), "=r"(r[2]), "=r"(r[3]) : "r"(addr));
}
__device__ __forceinline__ void mma16816(float* d, const uint32_t* a,
                                         uint32_t b0, uint32_t b1) {
    asm volatile(
        "mma.sync.aligned.m16n8k16.row.col.f32.bf16.bf16.f32 "
        "{%0,%1,%2,%3},{%4,%5,%6,%7},{%8,%9},{%0,%1,%2,%3};"
        : "+f"(d[0]), "+f"(d[1]), "+f"(d[2]), "+f"(d[3])
        : "r"(a[0]), "r"(a[1]), "r"(a[2]), "r"(a[3]), "r"(b0), "r"(b1));
}

// ------------------------- SSM parameter precompute -----------------------
__global__ void prep_kernel(const float* __restrict__ logAr,
                            const float* __restrict__ Aim,
                            const float* __restrict__ Bp,
                            const float* __restrict__ Cp,
                            const float* __restrict__ logdt) {
    int i = blockIdx.x * blockDim.x + threadIdx.x;
    if (i >= D_MODEL * STATE_N) return;
    int d = i >> 6;
    float dt  = expf(logdt[d]);
    float ar  = -expf(logAr[i]);
    float th  = dt * Aim[i];
    float mag = expf(dt * ar);
    float wrv = mag * cosf(th);
    float wiv = mag * sinf(th);
    g_wr[i] = wrv;
    g_wi[i] = wiv;
    g_cb[i] = Cp[i] * Bp[i] * dt;
    float xr = wrv, xi = wiv;
#pragma unroll
    for (int s = 0; s < 7; s++) {  // w^128
        float nr = xr * xr - xi * xi;
        float ni = 2.0f * xr * xi;
        xr = nr; xi = ni;
    }
    g_wLr[i] = xr;
    g_wLi[i] = xi;
}

// ------------------------- bf16 split conversion --------------------------
// A layout: [hi | hi | lo] ; W layout: [hi | lo | hi]
// TGT: 0=g_xcat(src=x) 1=g_ycat(src=g_y) 2=g_wincat 3=g_wgcat 4=g_wocat
template<int TGT>
__global__ __launch_bounds__(256) void conv_split(const float* __restrict__ src_ext) {
    const int i = blockIdx.x * 256 + threadIdx.x;   // one pair of elements
    const int m = i >> 8;
    const int c = (i & 255) * 2;
    const float* src = (TGT == 1) ? g_y : src_ext;
    __nv_bfloat16* dst = (TGT == 0) ? g_xcat : (TGT == 1) ? g_ycat :
                         (TGT == 2) ? g_wincat : (TGT == 3) ? g_wgcat : g_wocat;
    float2 v = *(const float2*)(src + (size_t)m * 512 + c);
    __nv_bfloat16 h0 = __float2bfloat16(v.x);
    __nv_bfloat16 h1 = __float2bfloat16(v.y);
    float r0 = v.x - __bfloat162float(h0);
    float r1 = v.y - __bfloat162float(h1);
    __nv_bfloat16 l0 = __float2bfloat16(r0);
    __nv_bfloat16 l1 = __float2bfloat16(r1);
    uint32_t hp, lp;
    {
        __nv_bfloat162 t = __halves2bfloat162(h0, h1);
        hp = *(uint32_t*)&t;
        __nv_bfloat162 t2 = __halves2bfloat162(l0, l1);
        lp = *(uint32_t*)&t2;
    }
    __nv_bfloat16* drow = dst + (size_t)m * KCAT + c;
    if (TGT >= 2) {   // weight: hi, lo, hi
        *(uint32_t*)(drow)        = hp;
        *(uint32_t*)(drow + 512)  = lp;
        *(uint32_t*)(drow + 1024) = hp;
    } else {          // activation: hi, hi, lo
        *(uint32_t*)(drow)        = hp;
        *(uint32_t*)(drow + 512)  = hp;
        *(uint32_t*)(drow + 1024) = lp;
    }
}

// ------------------------- ldmatrix + mma.sync bf16 GEMM ------------------
// C[8192x512] = Acat[8192x1536] · Wcat[512x1536]^T  (bf16 in, fp32 acc)
// MODE 0: g_u = ...      MODE 1: g_gate = sigmoid(... + b_gate)
// MODE 2: out = x + g_gate * (...)
#define BM 128
#define BN 128
#define BK 64
#define NCH (KCAT/BK)   // 24
#define SM_A 1024
#define SM_B 17408
#define GEMM_SMEM 33792

template<int MODE>
__global__ __launch_bounds__(256) void gemm_mma(
    const float* __restrict__ x_ext,     // x (MODE 2 epilogue)
    float* __restrict__ Cout_ext,        // d_out (MODE 2)
    const float* __restrict__ bgate) {   // b_gate (MODE 1)
    __shared__ __align__(128) char smem[GEMM_SMEM];
    const uint32_t sb = smem_u32(smem);
    const int tid  = threadIdx.x;
    const int wid  = tid >> 5, lane = tid & 31;
    const int wm   = wid & 3;          // 4 m-blocks of 32 rows
    const int wn   = wid >> 2;         // 2 n-blocks of 64 cols
    const int m0 = blockIdx.x * BM;
    const int n0 = blockIdx.y * BN;

    const __nv_bfloat16* Acat = (MODE == 2) ? g_ycat : g_xcat;
    const __nv_bfloat16* Wcat = (MODE == 0) ? g_wincat : (MODE == 1) ? g_wgcat : g_wocat;

    if (MODE == 1 && tid < BN) ((float*)smem)[tid] = bgate[n0 + tid];

    // ---- global->reg prefetch geometry (4 x 16B per thread per tile)
    const int r_base = tid >> 3;            // 0..31
    const int cb_off = (tid & 7) * 16;      // byte col within 128B row
    uint32_t sw_st[4];
#pragma unroll
    for (int i = 0; i < 4; i++)
        sw_st[i] = sw128((uint32_t)((r_base + i * 32) * 128 + cb_off));
    const char* Abase = (const char*)(Acat + (size_t)(m0 + r_base) * KCAT) + cb_off;
    const char* Bbase = (const char*)(Wcat + (size_t)(n0 + r_base) * KCAT) + cb_off;
    const size_t rstep = (size_t)32 * KCAT * 2;

    uint4 aR[4], bR[4];
#pragma unroll
    for (int i = 0; i < 4; i++) {
        aR[i] = *(const uint4*)(Abase + i * rstep);
        bR[i] = *(const uint4*)(Bbase + i * rstep);
    }

    // ---- ldmatrix per-lane base offsets
    const int grp = lane >> 3;
    const int l7  = lane & 7;
    // A x4: grp0: m0-7 kb0 | grp1: m8-15 kb0 | grp2: m0-7 kb16 | grp3: m8-15 kb16
    const uint32_t a_base = (uint32_t)((wm * 32 + ((grp & 1) ? 8 : 0) + l7) * 128
                                       + ((grp >> 1) ? 16 : 0));
    // B x4: grp0: n0-7 kb0 | grp1: n0-7 kb16 | grp2: n8-15 kb0 | grp3: n8-15 kb16
    const uint32_t b_base = (uint32_t)((wn * 64 + ((grp >> 1) ? 8 : 0) + l7) * 128
                                       + ((grp & 1) ? 16 : 0));

    float acc[2][8][4];
#pragma unroll
    for (int mf = 0; mf < 2; mf++)
#pragma unroll
        for (int nf = 0; nf < 8; nf++)
#pragma unroll
            for (int q = 0; q < 4; q++) acc[mf][nf][q] = 0.0f;

    for (int kc = 0; kc < NCH; kc++) {
        if (kc) __syncthreads();
#pragma unroll
        for (int i = 0; i < 4; i++) {
            asm volatile("st.shared.v4.b32 [%0], {%1,%2,%3,%4};"
                         :: "r"(sb + SM_A + sw_st[i]),
                            "r"(aR[i].x), "r"(aR[i].y), "r"(aR[i].z), "r"(aR[i].w) : "memory");
            asm volatile("st.shared.v4.b32 [%0], {%1,%2,%3,%4};"
                         :: "r"(sb + SM_B + sw_st[i]),
                            "r"(bR[i].x), "r"(bR[i].y), "r"(bR[i].z), "r"(bR[i].w) : "memory");
        }
        __syncthreads();
        if (kc + 1 < NCH) {   // prefetch next chunk during compute
            const char* An = Abase + (size_t)(kc + 1) * (BK * 2);
            const char* Bn = Bbase + (size_t)(kc + 1) * (BK * 2);
#pragma unroll
            for (int i = 0; i < 4; i++) {
                aR[i] = *(const uint4*)(An + i * rstep);
                bR[i] = *(const uint4*)(Bn + i * rstep);
            }
        }
#pragma unroll
        for (int s = 0; s < 4; s++) {      // 4 k-steps of 16
            uint32_t af[2][4];
#pragma unroll
            for (int mf = 0; mf < 2; mf++)
                ldmx4(af[mf], sb + SM_A + sw128(a_base + mf * 2048 + s * 32));
            uint32_t bf[4][4];
#pragma unroll
            for (int nq = 0; nq < 4; nq++)
                ldmx4(bf[nq], sb + SM_B + sw128(b_base + nq * 2048 + s * 32));
#pragma unroll
            for (int mf = 0; mf < 2; mf++)
#pragma unroll
                for (int nq = 0; nq < 4; nq++) {
                    mma16816(acc[mf][nq * 2],     af[mf], bf[nq][0], bf[nq][1]);
                    mma16816(acc[mf][nq * 2 + 1], af[mf], bf[nq][2], bf[nq][3]);
                }
        }
    }

    // ---- epilogue
    const int rrow = lane >> 2;
    const int rcol = (lane & 3) * 2;
    float* Cbase = (MODE == 0) ? g_u : (MODE == 1) ? g_gate : Cout_ext;
#pragma unroll
    for (int mf = 0; mf < 2; mf++) {
        const int mrow = m0 + wm * 32 + mf * 16 + rrow;
#pragma unroll
        for (int nf = 0; nf < 8; nf++) {
            const int ncl = wn * 64 + nf * 8 + rcol;   // 0..127 within tile
            const int col = n0 + ncl;
            float2 v0 = make_float2(acc[mf][nf][0], acc[mf][nf][1]);
            float2 v1 = make_float2(acc[mf][nf][2], acc[mf][nf][3]);
            if (MODE == 1) {
                float2 bb = *(const float2*)((const float*)smem + ncl);
                v0.x = __fdividef(1.0f, 1.0f + __expf(-(v0.x + bb.x)));
                v0.y = __fdividef(1.0f, 1.0f + __expf(-(v0.y + bb.y)));
                v1.x = __fdividef(1.0f, 1.0f + __expf(-(v1.x + bb.x)));
                v1.y = __fdividef(1.0f, 1.0f + __expf(-(v1.y + bb.y)));
            } else if (MODE == 2) {
                float2 x0 = *(const float2*)(x_ext + (size_t)mrow * 512 + col);
                float2 g0 = *(const float2*)(g_gate + (size_t)mrow * 512 + col);
                float2 x1 = *(const float2*)(x_ext + (size_t)(mrow + 8) * 512 + col);
                float2 g1 = *(const float2*)(g_gate + (size_t)(mrow + 8) * 512 + col);
                v0.x = fmaf(g0.x, v0.x, x0.x); v0.y = fmaf(g0.y, v0.y, x0.y);
                v1.x = fmaf(g1.x, v1.x, x1.x); v1.y = fmaf(g1.y, v1.y, x1.y);
            }
            *(float2*)(Cbase + (size_t)mrow * 512 + col)       = v0;
            *(float2*)(Cbase + (size_t)(mrow + 8) * 512 + col) = v1;
        }
    }
}

// ------------------------- scan phase 1 (f32x2-packed) --------------------
__global__ __launch_bounds__(256) void scan_phase1() {
    __shared__ float Us[LCH][32];
    const int tid  = threadIdx.x;
    const int dblk = blockIdx.x, c = blockIdx.y, b = blockIdx.z;
    const int dd = tid >> 3, j = tid & 7;
    const int d  = dblk * 32 + dd;

    const float* u = g_u + (size_t)(b * SEQ + c * LCH) * 512 + dblk * 32;
    for (int r = tid >> 5; r < LCH; r += 8)
        Us[r][tid & 31] = u[(size_t)r * 512 + (tid & 31)];
    __syncthreads();

    const int nbase = j * 8;
    unsigned long long wr2[4], wi2[4], nwi2[4], sr2[4], si2[4];
    {
        const float4* p = (const float4*)(g_wr + d * STATE_N + nbase);
        float4 t0 = p[0], t1 = p[1];
        wr2[0] = pk2(t0.x, t0.y); wr2[1] = pk2(t0.z, t0.w);
        wr2[2] = pk2(t1.x, t1.y); wr2[3] = pk2(t1.z, t1.w);
        p = (const float4*)(g_wi + d * STATE_N + nbase);
        t0 = p[0]; t1 = p[1];
        wi2[0] = pk2(t0.x, t0.y); wi2[1] = pk2(t0.z, t0.w);
        wi2[2] = pk2(t1.x, t1.y); wi2[3] = pk2(t1.z, t1.w);
        nwi2[0] = pk2(-t0.x, -t0.y); nwi2[1] = pk2(-t0.z, -t0.w);
        nwi2[2] = pk2(-t1.x, -t1.y); nwi2[3] = pk2(-t1.z, -t1.w);
    }
#pragma unroll
    for (int p = 0; p < 4; p++) { sr2[p] = 0ull; si2[p] = 0ull; }

#pragma unroll 4
    for (int t = 0; t < LCH; t++) {
        float ut = Us[t][dd];
        unsigned long long u2 = pk2(ut, ut);
#pragma unroll
        for (int p = 0; p < 4; p++) {
            unsigned long long mm = mul2(wi2[p], sr2[p]);
            unsigned long long tt = ffma2(nwi2[p], si2[p], u2);
            sr2[p] = ffma2(wr2[p], sr2[p], tt);
            si2[p] = ffma2(wr2[p], si2[p], mm);
        }
    }
    float2* Sp = g_S + ((size_t)(c * BD + b * D_MODEL + d)) * STATE_N + nbase;
#pragma unroll
    for (int p = 0; p < 4; p++) {
        float2 a = up2(sr2[p]), bb = up2(si2[p]);
        Sp[2 * p]     = make_float2(a.x, bb.x);
        Sp[2 * p + 1] = make_float2(a.y, bb.y);
    }
}

// ------------------------- scan phase 2 -----------------------------------
__global__ __launch_bounds__(256) void scan_phase2() {
    const int i  = blockIdx.x * blockDim.x + threadIdx.x;
    const int bd = i >> 6;
    const int n  = i & 63;
    const int d  = bd & (D_MODEL - 1);
    const float wLr = g_wLr[d * STATE_N + n];
    const float wLi = g_wLi[d * STATE_N + n];
    float er = 0.0f, ei = 0.0f;
#pragma unroll
    for (int c = 0; c < NC; c++) {
        const size_t idx = ((size_t)c * BD + bd) * STATE_N + n;
        g_E[idx] = make_float2(er, ei);
        float2 s = g_S[idx];
        float nr = fmaf(wLr, er, fmaf(-wLi, ei, s.x));
        float ni = fmaf(wLr, ei, fmaf(wLi, er, s.y));
        er = nr; ei = ni;
    }
}

// ------------------------- scan phase 3 (f32x2-packed) --------------------
__global__ __launch_bounds__(256) void scan_phase3(const float* __restrict__ Dp) {
    __shared__ float Us[LCH][32];
    const int tid  = threadIdx.x;
    const int dblk = blockIdx.x, c = blockIdx.y, b = blockIdx.z;
    const int dd = tid >> 3, j = tid & 7;
    const int d  = dblk * 32 + dd;

    const float* u = g_u + (size_t)(b * SEQ + c * LCH) * 512 + dblk * 32;
    for (int r = tid >> 5; r < LCH; r += 8)
        Us[r][tid & 31] = u[(size_t)r * 512 + (tid & 31)];
    __syncthreads();

    const int nbase = j * 8;
    unsigned long long wr2[4], wi2[4], nwi2[4], cb2[4], sr2[4], si2[4];
    {
        const float4* p = (const float4*)(g_wr + d * STATE_N + nbase);
        float4 t0 = p[0], t1 = p[1];
        wr2[0] = pk2(t0.x, t0.y); wr2[1] = pk2(t0.z, t0.w);
        wr2[2] = pk2(t1.x, t1.y); wr2[3] = pk2(t1.z, t1.w);
        p = (const float4*)(g_wi + d * STATE_N + nbase);
        t0 = p[0]; t1 = p[1];
        wi2[0] = pk2(t0.x, t0.y); wi2[1] = pk2(t0.z, t0.w);
        wi2[2] = pk2(t1.x, t1.y); wi2[3] = pk2(t1.z, t1.w);
        nwi2[0] = pk2(-t0.x, -t0.y); nwi2[1] = pk2(-t0.z, -t0.w);
        nwi2[2] = pk2(-t1.x, -t1.y); nwi2[3] = pk2(-t1.z, -t1.w);
        p = (const float4*)(g_cb + d * STATE_N + nbase);
        t0 = p[0]; t1 = p[1];
        cb2[0] = pk2(t0.x, t0.y); cb2[1] = pk2(t0.z, t0.w);
        cb2[2] = pk2(t1.x, t1.y); cb2[3] = pk2(t1.z, t1.w);
    }
    {
        const float4* Ep = (const float4*)(g_E + ((size_t)(c * BD + b * D_MODEL + d)) * STATE_N + nbase);
#pragma unroll
        for (int p = 0; p < 4; p++) {
            float4 e = Ep[p];   // (sr0, si0, sr1, si1)
            sr2[p] = pk2(e.x, e.z);
            si2[p] = pk2(e.y, e.w);
        }
    }
    const float Dd = Dp[d];
    float* yout = g_y + (size_t)(b * SEQ + c * LCH) * 512 + d;

#pragma unroll 4
    for (int t = 0; t < LCH; t++) {
        float ut = Us[t][dd];
        unsigned long long u2 = pk2(ut, ut);
        unsigned long long acc2 = 0ull;
#pragma unroll
        for (int p = 0; p < 4; p++) {
            unsigned long long mm = mul2(wi2[p], sr2[p]);
            unsigned long long tt = ffma2(nwi2[p], si2[p], u2);
            sr2[p] = ffma2(wr2[p], sr2[p], tt);
            si2[p] = ffma2(wr2[p], si2[p], mm);
            acc2   = ffma2(cb2[p], sr2[p], acc2);
        }
        float2 ap = up2(acc2);
        float accv = ap.x + ap.y;
        accv += __shfl_xor_sync(0xffffffffu, accv, 1, 8);
        accv += __shfl_xor_sync(0xffffffffu, accv, 2, 8);
        accv += __shfl_xor_sync(0xffffffffu, accv, 4, 8);
        if (j == 0) yout[(size_t)t * 512] = fmaf(Dd, ut, accv);
    }
}

// ------------------------- launch ----------------------------------------
extern "C" void kernel_launch(void* const* d_in, const int* in_sizes, int n_in,
                              void* d_out, int out_size) {
    const float* x      = (const float*)d_in[0];
    const float* logAr  = (const float*)d_in[1];
    const float* Aim    = (const float*)d_in[2];
    const float* Bp_    = (const float*)d_in[3];
    const float* Cp_    = (const float*)d_in[4];
    const float* Dp_    = (const float*)d_in[5];
    const float* logdt  = (const float*)d_in[6];
    const float* W_in   = (const float*)d_in[7];
    const float* W_out  = (const float*)d_in[8];
    const float* W_gate = (const float*)d_in[9];
    const float* b_gate = (const float*)d_in[10];
    float* out = (float*)d_out;

    prep_kernel<<<(D_MODEL * STATE_N + 255) / 256, 256>>>(logAr, Aim, Bp_, Cp_, logdt);
    conv_split<0><<<M_ROWS, 256>>>(x);
    conv_split<2><<<D_MODEL, 256>>>(W_in);
    conv_split<3><<<D_MODEL, 256>>>(W_gate);
    conv_split<4><<<D_MODEL, 256>>>(W_out);
    gemm_mma<0><<<dim3(M_ROWS / BM, D_MODEL / BN), 256>>>(nullptr, nullptr, nullptr);
    gemm_mma<1><<<dim3(M_ROWS / BM, D_MODEL / BN), 256>>>(nullptr, nullptr, b_gate);
    scan_phase1<<<dim3(D_MODEL / 32, NC, BATCH), 256>>>();
    scan_phase2<<<(BD * STATE_N) / 256, 256>>>();
    scan_phase3<<<dim3(D_MODEL / 32, NC, BATCH), 256>>>(Dp_);
    conv_split<1><<<M_ROWS, 256>>>(x);
    gemm_mma<2><<<dim3(M_ROWS / BM, D_MODEL / BN), 256>>>(x, out, nullptr);
}

// round 8
// speedup vs baseline: 1.8196x; 1.1739x over previous
#include <cuda_runtime.h>
#include <cuda_fp16.h>
#include <math.h>
#include <stdint.h>

#define D_MODEL 512
#define STATE_N 64
#define BATCH   4
#define SEQ     2048
#define M_ROWS  8192
#define NC      16
#define LCH     128
#define BD      2048
#define KCAT    1024           // 2 * 512 (fp16-split concatenated K)

// ------------------------- scratch (device globals) -----------------------
__device__ __align__(256) float  g_u   [M_ROWS*D_MODEL];
__device__ __align__(256) float  g_gate[M_ROWS*D_MODEL];
__device__ __align__(256) float2 g_S   [NC*BD*STATE_N];
__device__ __align__(256) float2 g_E   [NC*BD*STATE_N];
__device__ __align__(256) float  g_wr  [D_MODEL*STATE_N];
__device__ __align__(256) float  g_wi  [D_MODEL*STATE_N];
__device__ __align__(256) float  g_cb  [D_MODEL*STATE_N];
__device__ __align__(256) float  g_wLr [D_MODEL*STATE_N];
__device__ __align__(256) float  g_wLi [D_MODEL*STATE_N];
__device__ __align__(256) __half g_xcat  [M_ROWS*KCAT];
__device__ __align__(256) __half g_ycat  [M_ROWS*KCAT];
__device__ __align__(256) __half g_wincat[D_MODEL*KCAT];
__device__ __align__(256) __half g_wgcat [D_MODEL*KCAT];
__device__ __align__(256) __half g_wocat [D_MODEL*KCAT];

// ------------------------- f32x2 / ptx helpers ----------------------------
__device__ __forceinline__ unsigned long long ffma2(unsigned long long a,
                                                    unsigned long long b,
                                                    unsigned long long c) {
    unsigned long long d;
    asm("fma.rn.f32x2 %0, %1, %2, %3;" : "=l"(d) : "l"(a), "l"(b), "l"(c));
    return d;
}
__device__ __forceinline__ unsigned long long mul2(unsigned long long a,
                                                   unsigned long long b) {
    unsigned long long d;
    asm("mul.rn.f32x2 %0, %1, %2;" : "=l"(d) : "l"(a), "l"(b));
    return d;
}
__device__ __forceinline__ unsigned long long pk2(float x, float y) {
    unsigned long long r;
    asm("mov.b64 %0, {%1, %2};" : "=l"(r) : "r"(__float_as_uint(x)), "r"(__float_as_uint(y)));
    return r;
}
__device__ __forceinline__ float2 up2(unsigned long long v) {
    unsigned int lo, hi;
    asm("mov.b64 {%0, %1}, %2;" : "=r"(lo), "=r"(hi) : "l"(v));
    return make_float2(__uint_as_float(lo), __uint_as_float(hi));
}
__device__ __forceinline__ uint32_t smem_u32(const void* p) {
    uint32_t a;
    asm("{ .reg .u64 t; cvta.to.shared.u64 t, %1; cvt.u32.u64 %0, t; }" : "=r"(a) : "l"(p));
    return a;
}
__device__ __forceinline__ uint32_t sw128(uint32_t off) {
    return off ^ ((off >> 3) & 0x70);
}
__device__ __forceinline__ void ldmx4(uint32_t* r, uint32_t addr) {
    asm volatile("ldmatrix.sync.aligned.m8n8.x4.shared.b16 {%0,%1,%2,%3}, [%4];"
                 : "=r"(r[0]), "=r"(r[1]), "=r"(r[2]), "=r"(r[3]) : "r"(addr));
}
__device__ __forceinline__ void mma16816(float* d, const uint32_t* a,
                                         uint32_t b0, uint32_t b1) {
    asm volatile(
        "mma.sync.aligned.m16n8k16.row.col.f32.f16.f16.f32 "
        "{%0,%1,%2,%3},{%4,%5,%6,%7},{%8,%9},{%0,%1,%2,%3};"
        : "+f"(d[0]), "+f"(d[1]), "+f"(d[2]), "+f"(d[3])
        : "r"(a[0]), "r"(a[1]), "r"(a[2]), "r"(a[3]), "r"(b0), "r"(b1));
}

// ------------------------- SSM parameter precompute -----------------------
__global__ void prep_kernel(const float* __restrict__ logAr,
                            const float* __restrict__ Aim,
                            const float* __restrict__ Bp,
                            const float* __restrict__ Cp,
                            const float* __restrict__ logdt) {
    int i = blockIdx.x * blockDim.x + threadIdx.x;
    if (i >= D_MODEL * STATE_N) return;
    int d = i >> 6;
    float dt  = expf(logdt[d]);
    float ar  = -expf(logAr[i]);
    float th  = dt * Aim[i];
    float mag = expf(dt * ar);
    float wrv = mag * cosf(th);
    float wiv = mag * sinf(th);
    g_wr[i] = wrv;
    g_wi[i] = wiv;
    g_cb[i] = Cp[i] * Bp[i] * dt;
    float xr = wrv, xi = wiv;
#pragma unroll
    for (int s = 0; s < 7; s++) {  // w^128
        float nr = xr * xr - xi * xi;
        float ni = 2.0f * xr * xi;
        xr = nr; xi = ni;
    }
    g_wLr[i] = xr;
    g_wLi[i] = xi;
}

// ------------------------- fp16 split conversions -------------------------
// Activation rows: [hi(512) | lo(512)] ; Weight rows: [hi(512) | hi(512)]
__global__ __launch_bounds__(256) void conv_split_x(const float* __restrict__ src) {
    const int i = blockIdx.x * 256 + threadIdx.x;
    const int m = i >> 8;
    const int c = (i & 255) * 2;
    float2 v = *(const float2*)(src + (size_t)m * 512 + c);
    __half h0 = __float2half(v.x);
    __half h1 = __float2half(v.y);
    __half l0 = __float2half(v.x - __half2float(h0));
    __half l1 = __float2half(v.y - __half2float(h1));
    __half2 hp = __halves2half2(h0, h1);
    __half2 lp = __halves2half2(l0, l1);
    __half* drow = g_xcat + (size_t)m * KCAT + c;
    *(__half2*)(drow)       = hp;
    *(__half2*)(drow + 512) = lp;
}
__global__ __launch_bounds__(256) void conv_split_w(const float* __restrict__ Win,
                                                    const float* __restrict__ Wg,
                                                    const float* __restrict__ Wo) {
    const int w = blockIdx.y;
    const float* src = (w == 0) ? Win : (w == 1) ? Wg : Wo;
    __half* dst = (w == 0) ? g_wincat : (w == 1) ? g_wgcat : g_wocat;
    const int i = blockIdx.x * 256 + threadIdx.x;
    const int m = i >> 8;
    const int c = (i & 255) * 2;
    float2 v = *(const float2*)(src + (size_t)m * 512 + c);
    __half2 hp = __halves2half2(__float2half(v.x), __float2half(v.y));
    __half* drow = dst + (size_t)m * KCAT + c;
    *(__half2*)(drow)       = hp;
    *(__half2*)(drow + 512) = hp;
}

// ------------------------- ldmatrix + mma.sync fp16 GEMM ------------------
// C[8192x512] = Acat[8192x1024] · Wcat[512x1024]^T  (fp16 in, fp32 acc)
// MODE 0: g_u = ...      MODE 1: g_gate = sigmoid(... + b_gate)
// MODE 2: out = x + g_gate * (...)
#define BM 128
#define BN 128
#define BK 64
#define NCH (KCAT/BK)   // 16
#define SM_A 1024
#define SM_B 17408
#define GEMM_SMEM 33792

template<int MODE>
__global__ __launch_bounds__(256) void gemm_mma(
    const float* __restrict__ x_ext,     // x (MODE 2 epilogue)
    float* __restrict__ Cout_ext,        // d_out (MODE 2)
    const float* __restrict__ bgate) {   // b_gate (MODE 1)
    __shared__ __align__(128) char smem[GEMM_SMEM];
    const uint32_t sb = smem_u32(smem);
    const int tid  = threadIdx.x;
    const int wid  = tid >> 5, lane = tid & 31;
    const int wm   = wid & 3;          // 4 m-blocks of 32 rows
    const int wn   = wid >> 2;         // 2 n-blocks of 64 cols
    const int m0 = blockIdx.x * BM;
    const int n0 = blockIdx.y * BN;

    const __half* Acat = (MODE == 2) ? g_ycat : g_xcat;
    const __half* Wcat = (MODE == 0) ? g_wincat : (MODE == 1) ? g_wgcat : g_wocat;

    if (MODE == 1 && tid < BN) ((float*)smem)[tid] = bgate[n0 + tid];

    // ---- global->reg prefetch geometry (4 x 16B per thread per tile)
    const int r_base = tid >> 3;            // 0..31
    const int cb_off = (tid & 7) * 16;      // byte col within 128B row
    uint32_t sw_st[4];
#pragma unroll
    for (int i = 0; i < 4; i++)
        sw_st[i] = sw128((uint32_t)((r_base + i * 32) * 128 + cb_off));
    const char* Abase = (const char*)(Acat + (size_t)(m0 + r_base) * KCAT) + cb_off;
    const char* Bbase = (const char*)(Wcat + (size_t)(n0 + r_base) * KCAT) + cb_off;
    const size_t rstep = (size_t)32 * KCAT * 2;

    uint4 aR[4], bR[4];
#pragma unroll
    for (int i = 0; i < 4; i++) {
        aR[i] = *(const uint4*)(Abase + i * rstep);
        bR[i] = *(const uint4*)(Bbase + i * rstep);
    }

    // ---- ldmatrix per-lane base offsets
    const int grp = lane >> 3;
    const int l7  = lane & 7;
    const uint32_t a_base = (uint32_t)((wm * 32 + ((grp & 1) ? 8 : 0) + l7) * 128
                                       + ((grp >> 1) ? 16 : 0));
    const uint32_t b_base = (uint32_t)((wn * 64 + ((grp >> 1) ? 8 : 0) + l7) * 128
                                       + ((grp & 1) ? 16 : 0));

    float acc[2][8][4];
#pragma unroll
    for (int mf = 0; mf < 2; mf++)
#pragma unroll
        for (int nf = 0; nf < 8; nf++)
#pragma unroll
            for (int q = 0; q < 4; q++) acc[mf][nf][q] = 0.0f;

    for (int kc = 0; kc < NCH; kc++) {
        if (kc) __syncthreads();
#pragma unroll
        for (int i = 0; i < 4; i++) {
            asm volatile("st.shared.v4.b32 [%0], {%1,%2,%3,%4};"
                         :: "r"(sb + SM_A + sw_st[i]),
                            "r"(aR[i].x), "r"(aR[i].y), "r"(aR[i].z), "r"(aR[i].w) : "memory");
            asm volatile("st.shared.v4.b32 [%0], {%1,%2,%3,%4};"
                         :: "r"(sb + SM_B + sw_st[i]),
                            "r"(bR[i].x), "r"(bR[i].y), "r"(bR[i].z), "r"(bR[i].w) : "memory");
        }
        __syncthreads();
        if (kc + 1 < NCH) {   // prefetch next chunk during compute
            const char* An = Abase + (size_t)(kc + 1) * (BK * 2);
            const char* Bn = Bbase + (size_t)(kc + 1) * (BK * 2);
#pragma unroll
            for (int i = 0; i < 4; i++) {
                aR[i] = *(const uint4*)(An + i * rstep);
                bR[i] = *(const uint4*)(Bn + i * rstep);
            }
        }
#pragma unroll
        for (int s = 0; s < 4; s++) {      // 4 k-steps of 16
            uint32_t af[2][4];
#pragma unroll
            for (int mf = 0; mf < 2; mf++)
                ldmx4(af[mf], sb + SM_A + sw128(a_base + mf * 2048 + s * 32));
            uint32_t bf[4][4];
#pragma unroll
            for (int nq = 0; nq < 4; nq++)
                ldmx4(bf[nq], sb + SM_B + sw128(b_base + nq * 2048 + s * 32));
#pragma unroll
            for (int mf = 0; mf < 2; mf++)
#pragma unroll
                for (int nq = 0; nq < 4; nq++) {
                    mma16816(acc[mf][nq * 2],     af[mf], bf[nq][0], bf[nq][1]);
                    mma16816(acc[mf][nq * 2 + 1], af[mf], bf[nq][2], bf[nq][3]);
                }
        }
    }

    // ---- epilogue
    const int rrow = lane >> 2;
    const int rcol = (lane & 3) * 2;
    float* Cbase = (MODE == 0) ? g_u : (MODE == 1) ? g_gate : Cout_ext;
#pragma unroll
    for (int mf = 0; mf < 2; mf++) {
        const int mrow = m0 + wm * 32 + mf * 16 + rrow;
#pragma unroll
        for (int nf = 0; nf < 8; nf++) {
            const int ncl = wn * 64 + nf * 8 + rcol;   // 0..127 within tile
            const int col = n0 + ncl;
            float2 v0 = make_float2(acc[mf][nf][0], acc[mf][nf][1]);
            float2 v1 = make_float2(acc[mf][nf][2], acc[mf][nf][3]);
            if (MODE == 1) {
                float2 bb = *(const float2*)((const float*)smem + ncl);
                v0.x = __fdividef(1.0f, 1.0f + __expf(-(v0.x + bb.x)));
                v0.y = __fdividef(1.0f, 1.0f + __expf(-(v0.y + bb.y)));
                v1.x = __fdividef(1.0f, 1.0f + __expf(-(v1.x + bb.x)));
                v1.y = __fdividef(1.0f, 1.0f + __expf(-(v1.y + bb.y)));
            } else if (MODE == 2) {
                float2 x0 = *(const float2*)(x_ext + (size_t)mrow * 512 + col);
                float2 g0 = *(const float2*)(g_gate + (size_t)mrow * 512 + col);
                float2 x1 = *(const float2*)(x_ext + (size_t)(mrow + 8) * 512 + col);
                float2 g1 = *(const float2*)(g_gate + (size_t)(mrow + 8) * 512 + col);
                v0.x = fmaf(g0.x, v0.x, x0.x); v0.y = fmaf(g0.y, v0.y, x0.y);
                v1.x = fmaf(g1.x, v1.x, x1.x); v1.y = fmaf(g1.y, v1.y, x1.y);
            }
            *(float2*)(Cbase + (size_t)mrow * 512 + col)       = v0;
            *(float2*)(Cbase + (size_t)(mrow + 8) * 512 + col) = v1;
        }
    }
}

// ------------------------- scan phase 1 (f32x2-packed) --------------------
__global__ __launch_bounds__(256) void scan_phase1() {
    __shared__ float Us[LCH][32];
    const int tid  = threadIdx.x;
    const int dblk = blockIdx.x, c = blockIdx.y, b = blockIdx.z;
    const int dd = tid >> 3, j = tid & 7;
    const int d  = dblk * 32 + dd;

    const float* u = g_u + (size_t)(b * SEQ + c * LCH) * 512 + dblk * 32;
    for (int r = tid >> 5; r < LCH; r += 8)
        Us[r][tid & 31] = u[(size_t)r * 512 + (tid & 31)];
    __syncthreads();

    const int nbase = j * 8;
    unsigned long long wr2[4], wi2[4], nwi2[4], sr2[4], si2[4];
    {
        const float4* p = (const float4*)(g_wr + d * STATE_N + nbase);
        float4 t0 = p[0], t1 = p[1];
        wr2[0] = pk2(t0.x, t0.y); wr2[1] = pk2(t0.z, t0.w);
        wr2[2] = pk2(t1.x, t1.y); wr2[3] = pk2(t1.z, t1.w);
        p = (const float4*)(g_wi + d * STATE_N + nbase);
        t0 = p[0]; t1 = p[1];
        wi2[0] = pk2(t0.x, t0.y); wi2[1] = pk2(t0.z, t0.w);
        wi2[2] = pk2(t1.x, t1.y); wi2[3] = pk2(t1.z, t1.w);
        nwi2[0] = pk2(-t0.x, -t0.y); nwi2[1] = pk2(-t0.z, -t0.w);
        nwi2[2] = pk2(-t1.x, -t1.y); nwi2[3] = pk2(-t1.z, -t1.w);
    }
#pragma unroll
    for (int p = 0; p < 4; p++) { sr2[p] = 0ull; si2[p] = 0ull; }

#pragma unroll 4
    for (int t = 0; t < LCH; t++) {
        float ut = Us[t][dd];
        unsigned long long u2 = pk2(ut, ut);
#pragma unroll
        for (int p = 0; p < 4; p++) {
            unsigned long long mm = mul2(wi2[p], sr2[p]);
            unsigned long long tt = ffma2(nwi2[p], si2[p], u2);
            sr2[p] = ffma2(wr2[p], sr2[p], tt);
            si2[p] = ffma2(wr2[p], si2[p], mm);
        }
    }
    float2* Sp = g_S + ((size_t)(c * BD + b * D_MODEL + d)) * STATE_N + nbase;
#pragma unroll
    for (int p = 0; p < 4; p++) {
        float2 a = up2(sr2[p]), bb = up2(si2[p]);
        Sp[2 * p]     = make_float2(a.x, bb.x);
        Sp[2 * p + 1] = make_float2(a.y, bb.y);
    }
}

// ------------------------- scan phase 2 -----------------------------------
__global__ __launch_bounds__(256) void scan_phase2() {
    const int i  = blockIdx.x * blockDim.x + threadIdx.x;
    const int bd = i >> 6;
    const int n  = i & 63;
    const int d  = bd & (D_MODEL - 1);
    const float wLr = g_wLr[d * STATE_N + n];
    const float wLi = g_wLi[d * STATE_N + n];
    float er = 0.0f, ei = 0.0f;
#pragma unroll
    for (int c = 0; c < NC; c++) {
        const size_t idx = ((size_t)c * BD + bd) * STATE_N + n;
        g_E[idx] = make_float2(er, ei);
        float2 s = g_S[idx];
        float nr = fmaf(wLr, er, fmaf(-wLi, ei, s.x));
        float ni = fmaf(wLr, ei, fmaf(wLi, er, s.y));
        er = nr; ei = ni;
    }
}

// ------------------------- scan phase 3: scan + fused fp16 y-split --------
__global__ __launch_bounds__(256) void scan_phase3(const float* __restrict__ Dp) {
    __shared__ float Us[LCH][32];
    const int tid  = threadIdx.x;
    const int dblk = blockIdx.x, c = blockIdx.y, b = blockIdx.z;
    const int dd = tid >> 3, j = tid & 7;
    const int d  = dblk * 32 + dd;

    const float* u = g_u + (size_t)(b * SEQ + c * LCH) * 512 + dblk * 32;
    for (int r = tid >> 5; r < LCH; r += 8)
        Us[r][tid & 31] = u[(size_t)r * 512 + (tid & 31)];
    __syncthreads();

    const int nbase = j * 8;
    unsigned long long wr2[4], wi2[4], nwi2[4], cb2[4], sr2[4], si2[4];
    {
        const float4* p = (const float4*)(g_wr + d * STATE_N + nbase);
        float4 t0 = p[0], t1 = p[1];
        wr2[0] = pk2(t0.x, t0.y); wr2[1] = pk2(t0.z, t0.w);
        wr2[2] = pk2(t1.x, t1.y); wr2[3] = pk2(t1.z, t1.w);
        p = (const float4*)(g_wi + d * STATE_N + nbase);
        t0 = p[0]; t1 = p[1];
        wi2[0] = pk2(t0.x, t0.y); wi2[1] = pk2(t0.z, t0.w);
        wi2[2] = pk2(t1.x, t1.y); wi2[3] = pk2(t1.z, t1.w);
        nwi2[0] = pk2(-t0.x, -t0.y); nwi2[1] = pk2(-t0.z, -t0.w);
        nwi2[2] = pk2(-t1.x, -t1.y); nwi2[3] = pk2(-t1.z, -t1.w);
        p = (const float4*)(g_cb + d * STATE_N + nbase);
        t0 = p[0]; t1 = p[1];
        cb2[0] = pk2(t0.x, t0.y); cb2[1] = pk2(t0.z, t0.w);
        cb2[2] = pk2(t1.x, t1.y); cb2[3] = pk2(t1.z, t1.w);
    }
    {
        const float4* Ep = (const float4*)(g_E + ((size_t)(c * BD + b * D_MODEL + d)) * STATE_N + nbase);
#pragma unroll
        for (int p = 0; p < 4; p++) {
            float4 e = Ep[p];   // (sr0, si0, sr1, si1)
            sr2[p] = pk2(e.x, e.z);
            si2[p] = pk2(e.y, e.w);
        }
    }
    const float Dd = Dp[d];
    __half* ycat = g_ycat + (size_t)(b * SEQ + c * LCH) * KCAT + d;

#pragma unroll 4
    for (int t = 0; t < LCH; t++) {
        float ut = Us[t][dd];
        unsigned long long u2 = pk2(ut, ut);
        unsigned long long acc2 = 0ull;
#pragma unroll
        for (int p = 0; p < 4; p++) {
            unsigned long long mm = mul2(wi2[p], sr2[p]);
            unsigned long long tt = ffma2(nwi2[p], si2[p], u2);
            sr2[p] = ffma2(wr2[p], sr2[p], tt);
            si2[p] = ffma2(wr2[p], si2[p], mm);
            acc2   = ffma2(cb2[p], sr2[p], acc2);
        }
        float2 ap = up2(acc2);
        float accv = ap.x + ap.y;
        accv += __shfl_xor_sync(0xffffffffu, accv, 1, 8);
        accv += __shfl_xor_sync(0xffffffffu, accv, 2, 8);
        accv += __shfl_xor_sync(0xffffffffu, accv, 4, 8);
        if (j == 0) {
            float v = fmaf(Dd, ut, accv);
            __half h = __float2half(v);
            __half l = __float2half(v - __half2float(h));
            ycat[(size_t)t * KCAT]       = h;
            ycat[(size_t)t * KCAT + 512] = l;
        }
    }
}

// ------------------------- launch ----------------------------------------
extern "C" void kernel_launch(void* const* d_in, const int* in_sizes, int n_in,
                              void* d_out, int out_size) {
    const float* x      = (const float*)d_in[0];
    const float* logAr  = (const float*)d_in[1];
    const float* Aim    = (const float*)d_in[2];
    const float* Bp_    = (const float*)d_in[3];
    const float* Cp_    = (const float*)d_in[4];
    const float* Dp_    = (const float*)d_in[5];
    const float* logdt  = (const float*)d_in[6];
    const float* W_in   = (const float*)d_in[7];
    const float* W_out  = (const float*)d_in[8];
    const float* W_gate = (const float*)d_in[9];
    const float* b_gate = (const float*)d_in[10];
    float* out = (float*)d_out;

    prep_kernel<<<(D_MODEL * STATE_N + 255) / 256, 256>>>(logAr, Aim, Bp_, Cp_, logdt);
    conv_split_x<<<M_ROWS, 256>>>(x);
    conv_split_w<<<dim3(D_MODEL, 3), 256>>>(W_in, W_gate, W_out);
    gemm_mma<0><<<dim3(M_ROWS / BM, D_MODEL / BN), 256>>>(nullptr, nullptr, nullptr);
    gemm_mma<1><<<dim3(M_ROWS / BM, D_MODEL / BN), 256>>>(nullptr, nullptr, b_gate);
    scan_phase1<<<dim3(D_MODEL / 32, NC, BATCH), 256>>>();
    scan_phase2<<<(BD * STATE_N) / 256, 256>>>();
    scan_phase3<<<dim3(D_MODEL / 32, NC, BATCH), 256>>>(Dp_);
    gemm_mma<2><<<dim3(M_ROWS / BM, D_MODEL / BN), 256>>>(x, out, nullptr);
}